// round 4
// baseline (speedup 1.0000x reference)
#include <cuda_runtime.h>
#include <stdint.h>

// Problem constants (fixed shapes from reference)
#define NB 32
#define NS 32
#define NW 30
#define NE 300
#define NEV 75                   // float4 per embedding row (300 floats)
#define NSENT (NB * NS)          // 1024 sentences
#define EMB_ELEMS (NSENT * NW * NE)          // 9,216,000
#define OFF_SHARE  EMB_ELEMS
#define OFF_MASK   (2 * EMB_ELEMS)           // 18,432,000
#define OFF_WMASK  (OFF_MASK + NSENT * NW)   // 18,462,720
#define OFF_SMASK  (OFF_WMASK + NSENT * NW)  // 18,493,440

#define PARTS      6                          // CTAs per sentence
#define PART_ROWS  5                          // rows per CTA
#define PART_VEC   (PART_ROWS * NEV)          // 375 float4 per CTA
#define BLOCK      128
#define NITER      3                          // ceil(375/128)

__global__ __launch_bounds__(BLOCK) void embed_fused_kernel(
    const int* __restrict__ input_var,        // [1024*30] int32 tokens
    const float* __restrict__ W_emb,          // [50000*300]
    float* __restrict__ out)
{
    const int sent = blockIdx.x / PARTS;      // 0..1023
    const int part = blockIdx.x - sent * PARTS;
    const int tid  = threadIdx.x;
    const int r0   = part * PART_ROWS;

    __shared__ int s_tok[NW];
    __shared__ int s_tmp[NW];

    if (tid < NW) s_tok[tid] = input_var[sent * NW + tid];
    __syncthreads();

    // keep-mask: cumprod of nonzero (keep up to first zero)
    if (tid < NW) {
        bool keep = true;
        #pragma unroll
        for (int k = 0; k <= tid; k++) keep = keep && (s_tok[k] != 0);
        const int t = s_tok[tid];
        s_tmp[tid] = keep ? t : 0;
        if (part == 0) {
            out[OFF_MASK  + sent * NW + tid] = keep ? 1.0f : 0.0f;
            out[OFF_WMASK + sent * NW + tid] = (t != 0) ? 1.0f : 0.0f;
        }
    }
    if (part == 0 && tid == 0) {
        bool any = false;
        #pragma unroll
        for (int k = 0; k < NW; k++) any = any || (s_tok[k] != 0);
        out[OFF_SMASK + sent] = any ? 1.0f : 0.0f;
    }
    __syncthreads();

    const float4* __restrict__ emb4 = (const float4*)W_emb;
    float4* __restrict__ out_e = (float4*)out
        + (size_t)sent * (NW * NEV) + r0 * NEV;
    float4* __restrict__ out_s = (float4*)(out + OFF_SHARE)
        + (size_t)sent * (NW * NEV) + r0 * NEV;

    // Phase 1: batch independent gather loads (MLP = 3 per thread)
    float4 vals[NITER];
    #pragma unroll
    for (int i = 0; i < NITER; i++) {
        const int v = tid + i * BLOCK;
        if (v < PART_VEC) {
            const int wl = v / NEV;
            const int j  = v - wl * NEV;
            const int t  = s_tok[r0 + wl];
            vals[i] = emb4[(size_t)t * NEV + j];
        }
    }

    // Phase 2: streaming stores; rare truncated-token reload (predicated)
    #pragma unroll
    for (int i = 0; i < NITER; i++) {
        const int v = tid + i * BLOCK;
        if (v < PART_VEC) {
            const int wl = v / NEV;
            const int j  = v - wl * NEV;
            const int w  = r0 + wl;
            __stcs(&out_e[v], vals[i]);
            float4 x = vals[i];
            if (s_tmp[w] != s_tok[w]) x = emb4[(size_t)s_tmp[w] * NEV + j];
            __stcs(&out_s[v], x);
        }
    }
}

extern "C" void kernel_launch(void* const* d_in, const int* in_sizes, int n_in,
                              void* d_out, int out_size) {
    const int*   input_var = (const int*)d_in[0];
    const float* W_emb     = (const float*)d_in[1];
    float*       out       = (float*)d_out;

    embed_fused_kernel<<<NSENT * PARTS, BLOCK>>>(input_var, W_emb, out);
}